// round 10
// baseline (speedup 1.0000x reference)
#include <cuda_runtime.h>
#include <float.h>

#define NB 256
#define NC 4096
#define NK 32
#define THREADS 256
#define EPT 8           // 256 threads * 8 = 2048 = NC/2 columns per CTA
#define NPART (NB * 2)  // one partial per CTA

__device__ float g_partials[NPART];
__device__ unsigned int g_count;   // zero at load; reset by last CTA each run

__global__ __launch_bounds__(THREADS)
void mlaml_kernel(const float* __restrict__ x, const float* __restrict__ m,
                  const int* __restrict__ tgt, float* __restrict__ out) {
    __shared__ float  c_srt[NK];            // sorted descending thresholds
    __shared__ float  pre_plain[NK + 1];    // exclusive prefix sums of c_srt
    __shared__ float  c_tab[NK][32];        // lane-replicated (bank L = lane L)
    __shared__ float2 pre_tab[NK + 1][32];  // lane-replicated (Cpre[q], (float)q)
    __shared__ float  wsum[THREADS / 32];
    __shared__ int    V_sh;
    __shared__ int    isLast_sh;

    const int b    = blockIdx.x;   // row
    const int h    = blockIdx.y;   // column half
    const int tid  = threadIdx.x;
    const int lane = tid & 31;
    const int wid  = tid >> 5;

    const float* xr = x + (size_t)b * NC;
    const float* mr = m + (size_t)b * NC;

    // ---- Issue the target load FIRST so its DRAM latency overlaps row loads ----
    int t_raw = 0;
    if (wid == 0) t_raw = tgt[b * NK + lane];       // int32 targets

    // ---- Load this thread's 8 contiguous d_j = x_j - m_j ----
    const int j0 = h * (NC / 2) + tid * EPT;
    float4 xa = *reinterpret_cast<const float4*>(xr + j0);
    float4 xb = *reinterpret_cast<const float4*>(xr + j0 + 4);
    float4 ma = *reinterpret_cast<const float4*>(mr + j0);
    float4 mb = *reinterpret_cast<const float4*>(mr + j0 + 4);

    float ds[EPT];
    ds[0] = xa.x - ma.x; ds[1] = xa.y - ma.y;
    ds[2] = xa.z - ma.z; ds[3] = xa.w - ma.w;
    ds[4] = xb.x - mb.x; ds[5] = xb.y - mb.y;
    ds[6] = xb.z - mb.z; ds[7] = xb.w - mb.w;

    // ---- Warp 0: gather c_k = 1 - d_t, sort descending, prefix-sum ----
    if (wid == 0) {
        bool  valid = (t_raw > -1);
        float c     = -FLT_MAX;                     // invalid -> never active
        if (valid) c = 1.0f - (__ldg(xr + t_raw) - __ldg(mr + t_raw));
        unsigned vm = __ballot_sync(0xffffffffu, valid);
        if (lane == 0) V_sh = __popc(vm);

        // Bitonic sort ascending across the warp
        float v = c;
        #pragma unroll
        for (int k = 2; k <= 32; k <<= 1) {
            #pragma unroll
            for (int j = k >> 1; j > 0; j >>= 1) {
                float other = __shfl_xor_sync(0xffffffffu, v, j);
                bool  up       = ((lane & k) == 0);
                bool  iAmLower = ((lane & j) == 0);
                float mn = fminf(v, other), mx = fmaxf(v, other);
                v = (iAmLower == up) ? mn : mx;
            }
        }
        // Reverse to descending
        float dv = __shfl_sync(0xffffffffu, v, 31 - lane);
        c_srt[lane] = dv;
        // Inclusive scan of descending values
        float s = dv;
        #pragma unroll
        for (int off = 1; off < 32; off <<= 1) {
            float n = __shfl_up_sync(0xffffffffu, s, off);
            if (lane >= off) s += n;
        }
        pre_plain[lane + 1] = s;
        if (lane == 0) pre_plain[0] = 0.0f;
    }
    __syncthreads();

    // ---- Replicate tables per lane (conflict-free random access later) ----
    #pragma unroll
    for (int e = tid; e < NK * 32; e += THREADS)
        c_tab[e >> 5][e & 31] = c_srt[e >> 5];
    #pragma unroll
    for (int e = tid; e < (NK + 1) * 32; e += THREADS) {
        int idx = e >> 5;
        pre_tab[idx][e & 31] = make_float2(pre_plain[idx], (float)idx);
    }
    __syncthreads();

    // ---- Main loop: per element, branchless binary search over 32 thresholds ----
    float accA = 0.0f;   // sum of Cpre[q]
    float accB = 0.0f;   // sum of q * d
    #pragma unroll
    for (int e = 0; e < EPT; e++) {
        float t = -ds[e];
        int q = 0;
        if (c_tab[q + 15][lane] > t) q += 16;
        if (c_tab[q + 7][lane]  > t) q += 8;
        if (c_tab[q + 3][lane]  > t) q += 4;
        if (c_tab[q + 1][lane]  > t) q += 2;
        if (c_tab[q][lane]      > t) q += 1;
        if (c_tab[q][lane]      > t) q += 1;   // resolves final [q, q+1] interval
        float2 p = pre_tab[q][lane];
        accA += p.x;
        accB  = fmaf(p.y, ds[e], accB);
    }
    float local = accA + accB;

    // ---- Block reduce; STG partial to distinct address ----
    #pragma unroll
    for (int off = 16; off; off >>= 1)
        local += __shfl_xor_sync(0xffffffffu, local, off);
    if (lane == 0) wsum[wid] = local;
    __syncthreads();
    if (tid == 0) {
        float tot = 0.0f;
        #pragma unroll
        for (int i = 0; i < THREADS / 32; i++) tot += wsum[i];
        if (h == 0) tot -= (float)V_sh;   // exclude self terms (exactly 1 each)
        g_partials[h * NB + b] = tot;
        __threadfence();
        unsigned arrived = atomicAdd(&g_count, 1u);
        isLast_sh = (arrived == NPART - 1);
    }
    __syncthreads();

    // ---- Last CTA: reduce all 512 partials and write the scalar output ----
    if (isLast_sh) {
        volatile float* vp = g_partials;           // L1-bypassing loads
        float s = vp[tid] + vp[tid + THREADS];
        #pragma unroll
        for (int off = 16; off; off >>= 1)
            s += __shfl_xor_sync(0xffffffffu, s, off);
        if (lane == 0) wsum[wid] = s;
        __syncthreads();
        if (tid == 0) {
            float tot = 0.0f;
            #pragma unroll
            for (int i = 0; i < THREADS / 32; i++) tot += wsum[i];
            out[0] = tot * (1.0f / (float)NC);
            g_count = 0;                           // reset for next graph replay
        }
    }
}

extern "C" void kernel_launch(void* const* d_in, const int* in_sizes, int n_in,
                              void* d_out, int out_size) {
    const float* x   = (const float*)d_in[0];
    const float* m   = (const float*)d_in[1];
    const int*   tgt = (const int*)d_in[2];
    float*       out = (float*)d_out;

    mlaml_kernel<<<dim3(NB, 2), THREADS>>>(x, m, tgt, out);
}

// round 15
// speedup vs baseline: 1.0683x; 1.0683x over previous
#include <cuda_runtime.h>
#include <float.h>

#define NB 256
#define NC 4096
#define NK 32
#define THREADS 512
#define EPT 8           // 512 threads * 8 = 4096 = NC columns (one full row per CTA)
#define NBKT 8
#define PER_BKT (NB / NBKT)   // 32 arrivals per bucket

// Bucketed stage/counter arrays, 1KB stride -> distinct L2 slices (hash bits {8,10-27})
__device__ float        g_stage[NBKT * 256];   // use [i*256]
__device__ unsigned int g_cnt1[NBKT * 256];    // use [i*256]
__device__ unsigned int g_cnt2;                // 8 arrivals only

__global__ __launch_bounds__(THREADS)
void mlaml_kernel(const float* __restrict__ x, const float* __restrict__ m,
                  const int* __restrict__ tgt, float* __restrict__ out) {
    __shared__ float  c_srt[NK];            // sorted descending thresholds
    __shared__ float  pre_plain[NK + 1];    // exclusive prefix sums
    __shared__ float  c_tab[NK][32];        // lane-replicated (bank L = lane L)
    __shared__ float2 pre_tab[NK + 1][32];  // lane-replicated (Cpre[q], (float)q)
    __shared__ float  wsum[THREADS / 32];
    __shared__ int    V_sh;
    __shared__ int    isLast_sh;

    const int b    = blockIdx.x;   // row
    const int tid  = threadIdx.x;
    const int lane = tid & 31;
    const int wid  = tid >> 5;

    const float* xr = x + (size_t)b * NC;
    const float* mr = m + (size_t)b * NC;

    // ---- Target load first: DRAM latency overlaps the row loads ----
    int t_raw = 0;
    if (wid == 0) t_raw = tgt[b * NK + lane];       // int32 targets

    // ---- Load this thread's 8 contiguous d_j = x_j - m_j ----
    const int j0 = tid * EPT;
    float4 xa = *reinterpret_cast<const float4*>(xr + j0);
    float4 xb = *reinterpret_cast<const float4*>(xr + j0 + 4);
    float4 ma = *reinterpret_cast<const float4*>(mr + j0);
    float4 mb = *reinterpret_cast<const float4*>(mr + j0 + 4);

    float ds[EPT];
    ds[0] = xa.x - ma.x; ds[1] = xa.y - ma.y;
    ds[2] = xa.z - ma.z; ds[3] = xa.w - ma.w;
    ds[4] = xb.x - mb.x; ds[5] = xb.y - mb.y;
    ds[6] = xb.z - mb.z; ds[7] = xb.w - mb.w;

    // ---- Warp 0: gather c_k = 1 - d_t, bitonic sort desc, prefix-sum ----
    if (wid == 0) {
        bool  valid = (t_raw > -1);
        float c     = -FLT_MAX;                     // invalid -> never active
        if (valid) c = 1.0f - (__ldg(xr + t_raw) - __ldg(mr + t_raw));
        unsigned vm = __ballot_sync(0xffffffffu, valid);
        if (lane == 0) V_sh = __popc(vm);

        float v = c;
        #pragma unroll
        for (int k = 2; k <= 32; k <<= 1) {
            #pragma unroll
            for (int j = k >> 1; j > 0; j >>= 1) {
                float other = __shfl_xor_sync(0xffffffffu, v, j);
                bool  up       = ((lane & k) == 0);
                bool  iAmLower = ((lane & j) == 0);
                float mn = fminf(v, other), mx = fmaxf(v, other);
                v = (iAmLower == up) ? mn : mx;
            }
        }
        float dv = __shfl_sync(0xffffffffu, v, 31 - lane);   // descending
        c_srt[lane] = dv;
        float s = dv;                                         // inclusive scan
        #pragma unroll
        for (int off = 1; off < 32; off <<= 1) {
            float n = __shfl_up_sync(0xffffffffu, s, off);
            if (lane >= off) s += n;
        }
        pre_plain[lane + 1] = s;
        if (lane == 0) pre_plain[0] = 0.0f;
    }
    __syncthreads();

    // ---- Replicate tables per lane (conflict-free random access later) ----
    #pragma unroll
    for (int e = tid; e < NK * 32; e += THREADS)
        c_tab[e >> 5][e & 31] = c_srt[e >> 5];
    for (int e = tid; e < (NK + 1) * 32; e += THREADS) {
        int idx = e >> 5;
        pre_tab[idx][e & 31] = make_float2(pre_plain[idx], (float)idx);
    }
    __syncthreads();

    // ---- Main loop: branchless binary search over 32 sorted thresholds ----
    float accA = 0.0f;   // sum of Cpre[q]
    float accB = 0.0f;   // sum of q * d
    #pragma unroll
    for (int e = 0; e < EPT; e++) {
        float t = -ds[e];
        int q = 0;
        if (c_tab[q + 15][lane] > t) q += 16;
        if (c_tab[q + 7][lane]  > t) q += 8;
        if (c_tab[q + 3][lane]  > t) q += 4;
        if (c_tab[q + 1][lane]  > t) q += 2;
        if (c_tab[q][lane]      > t) q += 1;
        if (c_tab[q][lane]      > t) q += 1;   // resolves final [q, q+1]
        float2 p = pre_tab[q][lane];
        accA += p.x;
        accB  = fmaf(p.y, ds[e], accB);
    }
    float local = accA + accB;

    // ---- Block reduce ----
    #pragma unroll
    for (int off = 16; off; off >>= 1)
        local += __shfl_xor_sync(0xffffffffu, local, off);
    if (lane == 0) wsum[wid] = local;
    __syncthreads();

    // ---- Bucketed two-level arrival tree (8 parallel L2 slices) ----
    if (tid == 0) {
        float tot = 0.0f;
        #pragma unroll
        for (int i = 0; i < THREADS / 32; i++) tot += wsum[i];
        tot -= (float)V_sh;                 // self terms are exactly relu(1)=1
        const int bk = b & (NBKT - 1);
        atomicAdd(&g_stage[bk * 256], tot);
        __threadfence();
        unsigned a1 = atomicAdd(&g_cnt1[bk * 256], 1u);
        int last = 0;
        if (a1 == PER_BKT - 1) {
            unsigned a2 = atomicAdd(&g_cnt2, 1u);
            last = (a2 == NBKT - 1);
        }
        isLast_sh = last;
    }
    __syncthreads();

    // ---- Final CTA: sum the 8 stage slots, write out, reset state ----
    if (isLast_sh && tid == 0) {
        __threadfence();
        volatile float* vs = g_stage;
        float s = 0.0f;
        #pragma unroll
        for (int i = 0; i < NBKT; i++) s += vs[i * 256];
        out[0] = s * (1.0f / (float)NC);
        #pragma unroll
        for (int i = 0; i < NBKT; i++) {
            g_stage[i * 256] = 0.0f;
            g_cnt1[i * 256]  = 0u;
        }
        g_cnt2 = 0u;
    }
}

extern "C" void kernel_launch(void* const* d_in, const int* in_sizes, int n_in,
                              void* d_out, int out_size) {
    const float* x   = (const float*)d_in[0];
    const float* m   = (const float*)d_in[1];
    const int*   tgt = (const int*)d_in[2];
    float*       out = (float*)d_out;

    mlaml_kernel<<<NB, THREADS>>>(x, m, tgt, out);
}